// round 9
// baseline (speedup 1.0000x reference)
#include <cuda_runtime.h>
#include <math.h>

#define MAXN 100000
#define I_CNT 128
#define NMS_SMEM_N 28000
#define MTILE 256

typedef unsigned long long ull;

// ---------------- device scratch (no allocations allowed) ----------------
__device__ float g_tA[64 * MAXN];          // transposed activations [64][N]
__device__ float g_tB[64 * MAXN];
__device__ float g_mask_feats[16 * MAXN];  // transposed [16][N]
__device__ float g_kern_feats[16 * MAXN];  // transposed [16][N]
__device__ float g_s[4 * MAXN];            // nms fallback only
__device__ int   g_bstart[8];
__device__ int   g_topk[I_CNT];
__device__ float g_ctr[I_CNT * 3];
__device__ float g_ck[I_CNT * 16];
__device__ int   g_cb[I_CNT];
__device__ float g_weights[I_CNT * 337];
__device__ float g_beff[I_CNT * 16];
__device__ float g_feat[I_CNT * 35];
__device__ float g_pairA[I_CNT * I_CNT * 35];
__device__ float g_pairB[I_CNT * I_CNT * 35];
__device__ float g_sumF[3 * 64];           // staged tower stats (float)
__device__ float g_sumsqF[3 * 64];
__device__ double g_sumM[64];              // merge-branch stats
__device__ double g_sumsqM[64];
__device__ float g_meanM[64];
__device__ float g_rstdM[64];

// ---------------- f32x2 helpers ----------------
__device__ __forceinline__ ull pk2(float lo, float hi) {
    ull r; asm("mov.b64 %0, {%1, %2};" : "=l"(r) : "f"(lo), "f"(hi)); return r;
}
__device__ __forceinline__ void upk2(ull v, float& lo, float& hi) {
    asm("mov.b64 {%0, %1}, %2;" : "=f"(lo), "=f"(hi) : "l"(v));
}
__device__ __forceinline__ ull ffma2(ull a, ull b, ull c) {
    ull d; asm("fma.rn.f32x2 %0, %1, %2, %3;" : "=l"(d) : "l"(a), "l"(b), "l"(c)); return d;
}
__device__ __forceinline__ float fast_sigmoid(float x) {
    return __fdividef(1.f, 1.f + __expf(-x));
}

// ---------------- stats helpers ----------------
__global__ void zero_stats_kernel() {
    int t = threadIdx.x;
    if (t < 192) { g_sumF[t] = 0.f; g_sumsqF[t] = 0.f; }
    if (t < 64) { g_sumM[t] = 0.0; g_sumsqM[t] = 0.0; }
}

__global__ void finalize_statsM_kernel(int count, int dim) {
    int d = threadIdx.x;
    if (d < dim) {
        double m = g_sumM[d] / (double)count;
        double v = g_sumsqM[d] / (double)count - m * m;
        g_meanM[d] = (float)m;
        g_rstdM[d] = (float)(1.0 / sqrt(v + 1e-5));
    }
    if (d < 64) { g_sumM[d] = 0.0; g_sumsqM[d] = 0.0; }
}

// ---------------- layer 0: row-major input, smem transpose, fast fused stats ----------------
__global__ __launch_bounds__(256) void layer0_kernel(
    const float* __restrict__ in,
    const float* __restrict__ Wm, const float* __restrict__ Wk,
    float* __restrict__ out, int N)
{
    __shared__ float xs[256][33];
    __shared__ ull wp[1024];
    __shared__ float rb[8][257];

    int tid = threadIdx.x;
    int lane = tid & 31, wid = tid >> 5;
    for (int t = tid; t < 1024; t += 256) wp[t] = pk2(Wm[t], Wk[t]);

    int n0 = blockIdx.x * 256;
    int npts = N - n0; if (npts > 256) npts = 256;
    for (int idx = tid; idx < npts * 32; idx += 256)
        xs[idx >> 5][idx & 31] = in[(size_t)n0 * 32 + idx];
    __syncthreads();

    int n = n0 + tid;
    bool valid = (tid < npts);

    ull acc[32];
#pragma unroll
    for (int d = 0; d < 32; d++) acc[d] = 0ull;

    if (valid) {
#pragma unroll
        for (int c = 0; c < 32; c++) {
            float z = xs[tid][c];
            ull zz = pk2(z, z);
            const ull* w = &wp[c * 32];
#pragma unroll
            for (int d = 0; d < 32; d++) acc[d] = ffma2(zz, w[d], acc[d]);
        }
#pragma unroll
        for (int d = 0; d < 32; d++) {
            float lo, hi; upk2(acc[d], lo, hi);
            out[(size_t)d * N + n] = lo;
            out[(size_t)(32 + d) * N + n] = hi;
        }
    }

    // stats: 8 rounds of 8 channels via smem transpose, one warp per channel
#pragma unroll
    for (int r = 0; r < 8; r++) {
        __syncthreads();
#pragma unroll
        for (int c8 = 0; c8 < 8; c8++) {
            int ch = r * 8 + c8;
            float v = 0.f;
            if (valid) {
                float lo, hi;
                if (ch < 32) { upk2(acc[ch], lo, hi); v = lo; }
                else         { upk2(acc[ch - 32], lo, hi); v = hi; }
            }
            rb[c8][tid] = v;
        }
        __syncthreads();
        {
            int ch = r * 8 + wid;
            float s = 0.f, q = 0.f;
#pragma unroll
            for (int j = 0; j < 8; j++) {
                float v = rb[wid][lane + 32 * j];
                s += v; q = fmaf(v, v, q);
            }
#pragma unroll
            for (int o = 16; o > 0; o >>= 1) {
                s += __shfl_down_sync(0xffffffffu, s, o);
                q += __shfl_down_sync(0xffffffffu, q, o);
            }
            if (lane == 0) {
                atomicAdd(&g_sumF[ch], s);
                atomicAdd(&g_sumsqF[ch], q);
            }
        }
    }
}

// ---------------- BN layer: one tower per blockIdx.y, smem-staged, fast stats ----------------
template <bool STATS>
__global__ __launch_bounds__(256) void layerBN2_kernel(
    const float* __restrict__ in,
    const float* __restrict__ W0, const float* __restrict__ W1,
    float* __restrict__ out, int N, int rs, int ws_stage)
{
    __shared__ float xs[32][258];
    __shared__ float ws[1024];
    __shared__ float sm[32], sr[32];
    __shared__ float rb[8][257];

    int tid = threadIdx.x;
    int lane = tid & 31, wid = tid >> 5;
    int t = blockIdx.y;
    int cb = t * 32;
    const float* W = t ? W1 : W0;
    for (int i = tid; i < 1024; i += 256) ws[i] = W[i];
    if (tid < 32) {
        double m = (double)g_sumF[rs * 64 + cb + tid] / (double)N;
        double v = (double)g_sumsqF[rs * 64 + cb + tid] / (double)N - m * m;
        sm[tid] = (float)m;
        sr[tid] = (float)(1.0 / sqrt(v + 1e-5));
    }

    int n0 = blockIdx.x * 256;
    if ((n0 + 256 <= N) && ((N & 3) == 0)) {
        for (int idx = tid; idx < 32 * 64; idx += 256) {
            int c = idx >> 6, p4 = (idx & 63) * 4;
            float4 v = *(const float4*)(in + (size_t)(cb + c) * N + n0 + p4);
            xs[c][p4] = v.x; xs[c][p4 + 1] = v.y; xs[c][p4 + 2] = v.z; xs[c][p4 + 3] = v.w;
        }
    } else {
        for (int idx = tid; idx < 32 * 256; idx += 256) {
            int c = idx >> 8, p = idx & 255;
            int n = n0 + p;
            xs[c][p] = (n < N) ? in[(size_t)(cb + c) * N + n] : 0.f;
        }
    }
    __syncthreads();

    int n = n0 + tid;
    bool valid = (n < N);

    float acc[32];
#pragma unroll
    for (int d = 0; d < 32; d++) acc[d] = 0.f;

#pragma unroll
    for (int c = 0; c < 32; c++) {
        float x = fmaxf((xs[c][tid] - sm[c]) * sr[c], 0.f);
        const float* w = &ws[c * 32];
#pragma unroll
        for (int d = 0; d < 32; d++) acc[d] = fmaf(x, w[d], acc[d]);
    }
    if (valid) {
#pragma unroll
        for (int d = 0; d < 32; d++) out[(size_t)(cb + d) * N + n] = acc[d];
    }

    if (STATS) {
#pragma unroll
        for (int r = 0; r < 4; r++) {
            __syncthreads();
#pragma unroll
            for (int c8 = 0; c8 < 8; c8++)
                rb[c8][tid] = valid ? acc[r * 8 + c8] : 0.f;
            __syncthreads();
            {
                int ch = r * 8 + wid;
                float s = 0.f, q = 0.f;
#pragma unroll
                for (int j = 0; j < 8; j++) {
                    float v = rb[wid][lane + 32 * j];
                    s += v; q = fmaf(v, v, q);
                }
#pragma unroll
                for (int o = 16; o > 0; o >>= 1) {
                    s += __shfl_down_sync(0xffffffffu, s, o);
                    q += __shfl_down_sync(0xffffffffu, q, o);
                }
                if (lane == 0) {
                    atomicAdd(&g_sumF[ws_stage * 64 + cb + ch], s);
                    atomicAdd(&g_sumsqF[ws_stage * 64 + cb + ch], q);
                }
            }
        }
    }
}

// ---------------- output layer: one tower per blockIdx.y ----------------
__global__ __launch_bounds__(256) void layerOut2_kernel(
    const float* __restrict__ in,
    const float* __restrict__ W0, const float* __restrict__ W1,
    const float* __restrict__ b0, const float* __restrict__ b1,
    float* __restrict__ o0, float* __restrict__ o1, int N, int rs)
{
    __shared__ float xs[32][258];
    __shared__ float ws[512];
    __shared__ float sm[32], sr[32];
    __shared__ float bb[16];

    int tid = threadIdx.x;
    int t = blockIdx.y;
    int cb = t * 32;
    const float* W = t ? W1 : W0;
    const float* bias = t ? b1 : b0;
    float* out = t ? o1 : o0;
    for (int i = tid; i < 512; i += 256) ws[i] = W[i];
    if (tid < 32) {
        double m = (double)g_sumF[rs * 64 + cb + tid] / (double)N;
        double v = (double)g_sumsqF[rs * 64 + cb + tid] / (double)N - m * m;
        sm[tid] = (float)m;
        sr[tid] = (float)(1.0 / sqrt(v + 1e-5));
    }
    if (tid < 16) bb[tid] = bias[tid];

    int n0 = blockIdx.x * 256;
    if ((n0 + 256 <= N) && ((N & 3) == 0)) {
        for (int idx = tid; idx < 32 * 64; idx += 256) {
            int c = idx >> 6, p4 = (idx & 63) * 4;
            float4 v = *(const float4*)(in + (size_t)(cb + c) * N + n0 + p4);
            xs[c][p4] = v.x; xs[c][p4 + 1] = v.y; xs[c][p4 + 2] = v.z; xs[c][p4 + 3] = v.w;
        }
    } else {
        for (int idx = tid; idx < 32 * 256; idx += 256) {
            int c = idx >> 8, p = idx & 255;
            int n = n0 + p;
            xs[c][p] = (n < N) ? in[(size_t)(cb + c) * N + n] : 0.f;
        }
    }
    __syncthreads();

    int n = n0 + tid;
    if (n >= N) return;

    float acc[16];
#pragma unroll
    for (int d = 0; d < 16; d++) acc[d] = bb[d];

#pragma unroll
    for (int c = 0; c < 32; c++) {
        float x = fmaxf((xs[c][tid] - sm[c]) * sr[c], 0.f);
        const float* w = &ws[c * 16];
#pragma unroll
        for (int d = 0; d < 16; d++) acc[d] = fmaf(x, w[d], acc[d]);
    }
#pragma unroll
    for (int d = 0; d < 16; d++) out[(size_t)d * N + n] = acc[d];
}

// ---------------- merge-branch layer ----------------
template <int DIN, int DOUT, bool BN, bool STATS, bool BIAS>
__global__ __launch_bounds__(256) void layerM_kernel(
    const float* __restrict__ in, const float* __restrict__ W,
    const float* __restrict__ bias, float* __restrict__ out, int N)
{
    __shared__ float Ws[DIN * DOUT];
    __shared__ float sb[DOUT];
    __shared__ float sm[DIN], sr[DIN];
    __shared__ double bs[DOUT], bq[DOUT];

    for (int t = threadIdx.x; t < DIN * DOUT; t += blockDim.x) Ws[t] = W[t];
    if (threadIdx.x < DOUT) sb[threadIdx.x] = BIAS ? bias[threadIdx.x] : 0.f;
    if (BN && threadIdx.x < DIN) {
        sm[threadIdx.x] = g_meanM[threadIdx.x];
        sr[threadIdx.x] = g_rstdM[threadIdx.x];
    }
    if (STATS && threadIdx.x < DOUT) { bs[threadIdx.x] = 0.0; bq[threadIdx.x] = 0.0; }
    __syncthreads();

    int n = blockIdx.x * blockDim.x + threadIdx.x;
    bool valid = (n < N);
    float acc[DOUT];
#pragma unroll
    for (int d = 0; d < DOUT; d++) acc[d] = sb[d];

    if (valid) {
#pragma unroll
        for (int c = 0; c < DIN; c++) {
            float xv = in[(size_t)n * DIN + c];
            if (BN) xv = fmaxf((xv - sm[c]) * sr[c], 0.f);
#pragma unroll
            for (int d = 0; d < DOUT; d++) acc[d] = fmaf(xv, Ws[c * DOUT + d], acc[d]);
        }
#pragma unroll
        for (int d = 0; d < DOUT; d++) out[(size_t)n * DOUT + d] = acc[d];
    }

    if (STATS) {
#pragma unroll
        for (int d = 0; d < DOUT; d++) {
            float v = valid ? acc[d] : 0.f;
            float v2 = v * v;
#pragma unroll
            for (int o = 16; o > 0; o >>= 1) {
                v  += __shfl_down_sync(0xffffffffu, v, o);
                v2 += __shfl_down_sync(0xffffffffu, v2, o);
            }
            if ((threadIdx.x & 31) == 0) {
                atomicAdd(&bs[d], (double)v);
                atomicAdd(&bq[d], (double)v2);
            }
        }
        __syncthreads();
        if (threadIdx.x < DOUT) {
            atomicAdd(&g_sumM[threadIdx.x], bs[threadIdx.x]);
            atomicAdd(&g_sumsqM[threadIdx.x], bq[threadIdx.x]);
        }
    }
}

// ---------------- batch ranges ----------------
__global__ void batch_ranges_kernel(const int* __restrict__ bidx, int N) {
    int n = blockIdx.x * blockDim.x + threadIdx.x;
    if (n >= N) return;
    int b = bidx[n];
    int pb = (n == 0) ? -1 : bidx[n - 1];
    for (int x = pb + 1; x <= b; x++) g_bstart[x] = n;
    if (n == N - 1) for (int x = b + 1; x <= 4; x++) g_bstart[x] = N;
}

// ---------------- NMS v3b: lazy argmax (cache-preserving reduce), x cache, bbox early-out ----------------
__global__ __launch_bounds__(512) void nms_kernel(
    const float* __restrict__ heat, const float* __restrict__ coords, int N)
{
    extern __shared__ float dynsh[];
    __shared__ float wv[16];
    __shared__ int   wix[16];
    __shared__ float scx, scy, scz;

    int b = blockIdx.x, tid = threadIdx.x;
    int s0 = g_bstart[b], s1 = g_bstart[b + 1];
    int cnt = s1 - s0;
    bool inS = (cnt <= NMS_SMEM_N);
    float* sl = inS ? dynsh : (g_s + (size_t)b * MAXN);
    float* xl = dynsh + NMS_SMEM_N;   // only valid when inS

    // (bv, bi) is ALWAYS "max over this thread's own elements". Never clobbered.
    float bv = -INFINITY; int bi = 0;
    for (int l = tid; l < cnt; l += 512) {
        int n = s0 + l;
        float v = heat[n];
        sl[l] = v;
        float xv = coords[(size_t)n * 3];
        if (inS) xl[l] = xv;
        if (v > bv) { bv = v; bi = n; }
    }

    for (int k = 0; ; k++) {
        // block reduce on TEMPORARIES so the per-thread cache survives
        float rv = bv; int ri = bi;
#pragma unroll
        for (int o = 16; o > 0; o >>= 1) {
            float ov = __shfl_down_sync(0xffffffffu, rv, o);
            int   oi = __shfl_down_sync(0xffffffffu, ri, o);
            if (ov > rv || (ov == rv && oi < ri)) { rv = ov; ri = oi; }
        }
        if ((tid & 31) == 0) { wv[tid >> 5] = rv; wix[tid >> 5] = ri; }
        __syncthreads();
        if (tid < 16) {
            float v = wv[tid]; int ix = wix[tid];
#pragma unroll
            for (int o = 8; o > 0; o >>= 1) {
                float ov = __shfl_down_sync(0xffffu, v, o, 16);
                int   oi = __shfl_down_sync(0xffffu, ix, o, 16);
                if (ov > v || (ov == v && oi < ix)) { v = ov; ix = oi; }
            }
            if (tid == 0) {
                g_topk[b * 32 + k] = ix;
                scx = coords[(size_t)ix * 3];
                scy = coords[(size_t)ix * 3 + 1];
                scz = coords[(size_t)ix * 3 + 2];
            }
        }
        __syncthreads();
        if (k == 31) break;

        float cx = scx, cy = scy, cz = scz;
        bool changed = false;
        for (int l = tid; l < cnt; l += 512) {
            float xv = inS ? xl[l] : coords[(size_t)(s0 + l) * 3];
            float dx = __fadd_rn(xv, -cx);
            if (__fmul_rn(dx, dx) < 0.09f) {
                float v = sl[l];
                if (v != -INFINITY) {
                    int n = s0 + l;
                    float dy = __fadd_rn(coords[(size_t)n * 3 + 1], -cy);
                    float dz = __fadd_rn(coords[(size_t)n * 3 + 2], -cz);
                    float d2 = __fadd_rn(__fadd_rn(__fmul_rn(dx, dx), __fmul_rn(dy, dy)),
                                         __fmul_rn(dz, dz));
                    if (d2 < 0.09f) { sl[l] = -INFINITY; changed = true; }
                }
            }
        }
        if (changed) {   // rescan only if my own elements changed
            bv = -INFINITY; bi = 0;
            for (int l = tid; l < cnt; l += 512) {
                float v = sl[l];
                int n = s0 + l;
                if (v > bv || (v == bv && n < bi)) { bv = v; bi = n; }
            }
        }
        // The selected point's owner always sees d2 == 0 < 0.09 and rescans,
        // so it can never be re-selected from a stale cache.
    }
}

// ---------------- gather selected candidates ----------------
__global__ void gather_kernel(const float* __restrict__ coords, const int* __restrict__ bidx, int N) {
    int i = threadIdx.x;
    int idx = g_topk[i];
    float c0 = coords[idx * 3], c1 = coords[idx * 3 + 1], c2 = coords[idx * 3 + 2];
    g_ctr[i * 3] = c0; g_ctr[i * 3 + 1] = c1; g_ctr[i * 3 + 2] = c2;
    g_cb[i] = bidx[idx];
    for (int c = 0; c < 16; c++) {
        float kf = g_kern_feats[(size_t)c * N + idx];
        float mf = g_mask_feats[(size_t)c * N + idx];
        g_ck[i * 16 + c] = kf;
        g_feat[i * 35 + c] = kf;
        g_feat[i * 35 + 16 + c] = mf;
    }
    g_feat[i * 35 + 32] = c0;
    g_feat[i * 35 + 33] = c1;
    g_feat[i * 35 + 34] = c2;
}

// ---------------- weight generator ----------------
__global__ void weights_kernel(const float* __restrict__ Wwg, const float* __restrict__ bwg) {
    int i = blockIdx.x, j = threadIdx.x;
    if (j >= 337) return;
    float a = bwg[j];
#pragma unroll
    for (int c = 0; c < 16; c++) a = fmaf(g_ck[i * 16 + c], Wwg[c * 337 + j], a);
    g_weights[i * 337 + j] = a;
}

__global__ void beff_kernel() {
    int i = blockIdx.x, h = threadIdx.x;
    const float* wi = g_weights + i * 337;
    float b = wi[304 + h];
#pragma unroll
    for (int p = 0; p < 3; p++) b -= g_ctr[i * 3 + p] * wi[(16 + p) * 16 + h];
    g_beff[i * 16 + h] = b;
}

// ---------------- dynamic-conv masks: 256-point tiles ----------------
__global__ __launch_bounds__(256) void masks_kernel(
    const float* __restrict__ coords, float* __restrict__ out, int N, int outw)
{
    extern __shared__ float dyn[];
    float* zs = dyn;                    // [19][MTILE+2]
    float* ot = dyn + 19 * (MTILE + 2); // [32][MTILE+1]

    int i_base = blockIdx.y * 32;
    int n0 = blockIdx.x * MTILE;
    int tid = threadIdx.x;
    int i_local = tid >> 3;
    int hg = tid & 7;
    int i = i_base + i_local;
    int h0 = hg * 2;

    const float* wi = g_weights + i * 337;
    ull w0[19], w1[19];
#pragma unroll
    for (int r = 0; r < 19; r++) {
        float a = wi[r * 16 + h0], b = wi[r * 16 + h0 + 1];
        w0[r] = pk2(a, a);
        w1[r] = pk2(b, b);
    }
    float be0f = g_beff[i * 16 + h0], be1f = g_beff[i * 16 + h0 + 1];
    ull be0 = pk2(be0f, be0f), be1 = pk2(be1f, be1f);
    float w2a = wi[320 + h0], w2b = wi[320 + h0 + 1];
    float b2 = wi[336];

    for (int idx = tid; idx < 16 * MTILE; idx += 256) {
        int c = idx >> 8, p = idx & (MTILE - 1);
        int n = n0 + p;
        zs[c * (MTILE + 2) + p] = (n < N) ? g_mask_feats[(size_t)c * N + n] : 0.f;
    }
    for (int idx = tid; idx < MTILE * 3; idx += 256) {
        int p = idx / 3, c = idx % 3;
        int n = n0 + p;
        zs[(16 + c) * (MTILE + 2) + p] = (n < N) ? coords[(size_t)n * 3 + c] : 0.f;
    }
    __syncthreads();

#pragma unroll 2
    for (int pp = 0; pp < MTILE / 2; pp++) {
        ull a0 = be0, a1 = be1;
#pragma unroll
        for (int r = 0; r < 19; r++) {
            ull z = *(const ull*)&zs[r * (MTILE + 2) + pp * 2];
            a0 = ffma2(z, w0[r], a0);
            a1 = ffma2(z, w1[r], a1);
        }
        float a0l, a0h, a1l, a1h;
        upk2(a0, a0l, a0h);
        upk2(a1, a1l, a1h);
        float pl = fmaf(fmaxf(a0l, 0.f), w2a, fmaxf(a1l, 0.f) * w2b);
        float ph = fmaf(fmaxf(a0h, 0.f), w2a, fmaxf(a1h, 0.f) * w2b);
        pl += __shfl_down_sync(0xffffffffu, pl, 4, 8);
        ph += __shfl_down_sync(0xffffffffu, ph, 4, 8);
        pl += __shfl_down_sync(0xffffffffu, pl, 2, 8);
        ph += __shfl_down_sync(0xffffffffu, ph, 2, 8);
        pl += __shfl_down_sync(0xffffffffu, pl, 1, 8);
        ph += __shfl_down_sync(0xffffffffu, ph, 1, 8);
        if (hg == 0) {
            ot[i_local * (MTILE + 1) + pp * 2]     = fast_sigmoid(pl + b2);
            ot[i_local * (MTILE + 1) + pp * 2 + 1] = fast_sigmoid(ph + b2);
        }
    }
    __syncthreads();

    for (int idx = tid; idx < 32 * MTILE; idx += 256) {
        int il = idx >> 8, p = idx & (MTILE - 1);
        int n = n0 + p;
        if (n < N) out[(size_t)(i_base + il) * outw + n] = ot[il * (MTILE + 1) + p];
    }
}

// ---------------- merge branch ----------------
__global__ void diff_kernel() {
    int p = blockIdx.x * blockDim.x + threadIdx.x;
    if (p >= I_CNT * I_CNT) return;
    int i = p >> 7, j = p & 127;
#pragma unroll
    for (int c = 0; c < 35; c++)
        g_pairA[(size_t)p * 35 + c] = fmaxf(fabsf(g_feat[i * 35 + c] - g_feat[j * 35 + c]), 1e-6f);
}

__global__ void merge_out_kernel(const float* __restrict__ WgOut, const float* __restrict__ bg,
                                 float* __restrict__ out, int N, int outw) {
    int p = blockIdx.x * blockDim.x + threadIdx.x;
    if (p >= I_CNT * I_CNT) return;
    int i = p >> 7, j = p & 127;
    float a = bg[0];
#pragma unroll
    for (int c = 0; c < 35; c++) {
        float xv = g_pairB[(size_t)p * 35 + c];
        xv = fmaxf((xv - g_meanM[c]) * g_rstdM[c], 0.f);
        a = fmaf(xv, WgOut[c], a);
    }
    float m = (g_cb[i] != g_cb[j]) ? 0.f : fast_sigmoid(a);
    out[(size_t)i * outw + N + j] = m;
}

// ---------------- launcher ----------------
extern "C" void kernel_launch(void* const* d_in, const int* in_sizes, int n_in,
                              void* d_out, int out_size)
{
    const float* output_feats = (const float*)d_in[0];
    const float* coords       = (const float*)d_in[1];
    const float* heat         = (const float*)d_in[2];
    const int*   batch_idxs   = (const int*)d_in[3];
    const float* Wm     = (const float*)d_in[4];
    const float* Wm_out = (const float*)d_in[5];
    const float* bm_out = (const float*)d_in[6];
    const float* Wk     = (const float*)d_in[7];
    const float* Wk_out = (const float*)d_in[8];
    const float* bk_out = (const float*)d_in[9];
    const float* Wg     = (const float*)d_in[10];
    const float* Wg_out = (const float*)d_in[11];
    const float* bg_out = (const float*)d_in[12];
    const float* Wwg    = (const float*)d_in[13];
    const float* bwg    = (const float*)d_in[14];
    float* out = (float*)d_out;

    int N = in_sizes[2];
    int outw = N + I_CNT;
    int nb = (N + 255) / 256;

    float *tA, *tB, *maskf, *kernf, *pairA, *pairB;
    cudaGetSymbolAddress((void**)&tA,    g_tA);
    cudaGetSymbolAddress((void**)&tB,    g_tB);
    cudaGetSymbolAddress((void**)&maskf, g_mask_feats);
    cudaGetSymbolAddress((void**)&kernf, g_kern_feats);
    cudaGetSymbolAddress((void**)&pairA, g_pairA);
    cudaGetSymbolAddress((void**)&pairB, g_pairB);

    const int MASK_SMEM = (19 * (MTILE + 2) + 32 * (MTILE + 1)) * (int)sizeof(float);
    const int NMS_SMEM = 2 * NMS_SMEM_N * (int)sizeof(float);

    static cudaStream_t s1;
    static cudaEvent_t evFork1, evJoin1, evFork2, evJoin2;
    static bool init_done = false;
    if (!init_done) {
        cudaFuncSetAttribute(nms_kernel, cudaFuncAttributeMaxDynamicSharedMemorySize,
                             NMS_SMEM);
        cudaFuncSetAttribute(masks_kernel, cudaFuncAttributeMaxDynamicSharedMemorySize,
                             MASK_SMEM);
        cudaStreamCreateWithFlags(&s1, cudaStreamNonBlocking);
        cudaEventCreateWithFlags(&evFork1, cudaEventDisableTiming);
        cudaEventCreateWithFlags(&evJoin1, cudaEventDisableTiming);
        cudaEventCreateWithFlags(&evFork2, cudaEventDisableTiming);
        cudaEventCreateWithFlags(&evJoin2, cudaEventDisableTiming);
        init_done = true;
    }

    batch_ranges_kernel<<<nb, 256>>>(batch_idxs, N);

    cudaEventRecord(evFork1, 0);
    cudaStreamWaitEvent(s1, evFork1, 0);
    nms_kernel<<<4, 512, NMS_SMEM, s1>>>(heat, coords, N);
    cudaEventRecord(evJoin1, s1);

    zero_stats_kernel<<<1, 192>>>();

    // tower chain: fused stats, no finalize launches (consumers read raw sums)
    dim3 g2(nb, 2);
    layer0_kernel<<<nb, 256>>>(output_feats, Wm, Wk, tA, N);
    layerBN2_kernel<true><<<g2, 256>>>(tA, Wm + 1024, Wk + 1024, tB, N, 0, 1);
    layerBN2_kernel<true><<<g2, 256>>>(tB, Wm + 2048, Wk + 2048, tA, N, 1, 2);
    layerOut2_kernel<<<g2, 256>>>(tA, Wm_out, Wk_out, bm_out, bk_out, maskf, kernf, N, 2);

    cudaStreamWaitEvent(0, evJoin1, 0);
    gather_kernel<<<1, 128>>>(coords, batch_idxs, N);
    weights_kernel<<<128, 352>>>(Wwg, bwg);

    cudaEventRecord(evFork2, 0);
    cudaStreamWaitEvent(s1, evFork2, 0);
    diff_kernel<<<64, 256, 0, s1>>>();
    layerM_kernel<35, 35, false, true, false><<<64, 256, 0, s1>>>(pairA, Wg,        nullptr, pairB, I_CNT * I_CNT);
    finalize_statsM_kernel<<<1, 64, 0, s1>>>(I_CNT * I_CNT, 35);
    layerM_kernel<35, 35, true,  true, false><<<64, 256, 0, s1>>>(pairB, Wg + 1225, nullptr, pairA, I_CNT * I_CNT);
    finalize_statsM_kernel<<<1, 64, 0, s1>>>(I_CNT * I_CNT, 35);
    layerM_kernel<35, 35, true,  true, false><<<64, 256, 0, s1>>>(pairA, Wg + 2450, nullptr, pairB, I_CNT * I_CNT);
    finalize_statsM_kernel<<<1, 64, 0, s1>>>(I_CNT * I_CNT, 35);
    merge_out_kernel<<<64, 256, 0, s1>>>(Wg_out, bg_out, out, N, outw);
    cudaEventRecord(evJoin2, s1);

    beff_kernel<<<128, 16>>>();
    dim3 mg((N + MTILE - 1) / MTILE, 4);
    masks_kernel<<<mg, 256, MASK_SMEM>>>(coords, out, N, outw);

    cudaStreamWaitEvent(0, evJoin2, 0);
}

// round 10
// speedup vs baseline: 1.1816x; 1.1816x over previous
#include <cuda_runtime.h>
#include <math.h>

#define MAXN 100000
#define I_CNT 128
#define NMS_SMEM_N 28000
#define MTILE 256

typedef unsigned long long ull;

// ---------------- device scratch (no allocations allowed) ----------------
__device__ float g_tA[64 * MAXN];          // transposed activations [64][N]
__device__ float g_tB[64 * MAXN];
__device__ float g_mask_feats[16 * MAXN];  // transposed [16][N]
__device__ float g_kern_feats[16 * MAXN];  // transposed [16][N]
__device__ float g_s[4 * MAXN];            // nms fallback only
__device__ int   g_bstart[8];
__device__ int   g_topk[I_CNT];
__device__ float g_ctr[I_CNT * 3];
__device__ float g_ck[I_CNT * 16];
__device__ int   g_cb[I_CNT];
__device__ float g_weights[I_CNT * 337];
__device__ float g_beff[I_CNT * 16];
__device__ float g_feat[I_CNT * 35];
__device__ float g_pairA[I_CNT * I_CNT * 35];
__device__ float g_pairB[I_CNT * I_CNT * 35];
__device__ float g_sumF[3 * 64];           // staged tower stats (float)
__device__ float g_sumsqF[3 * 64];
__device__ double g_sumM[64];              // merge-branch stats
__device__ double g_sumsqM[64];
__device__ float g_meanM[64];
__device__ float g_rstdM[64];

// ---------------- f32x2 helpers ----------------
__device__ __forceinline__ ull pk2(float lo, float hi) {
    ull r; asm("mov.b64 %0, {%1, %2};" : "=l"(r) : "f"(lo), "f"(hi)); return r;
}
__device__ __forceinline__ void upk2(ull v, float& lo, float& hi) {
    asm("mov.b64 {%0, %1}, %2;" : "=f"(lo), "=f"(hi) : "l"(v));
}
__device__ __forceinline__ ull ffma2(ull a, ull b, ull c) {
    ull d; asm("fma.rn.f32x2 %0, %1, %2, %3;" : "=l"(d) : "l"(a), "l"(b), "l"(c)); return d;
}
__device__ __forceinline__ float fast_sigmoid(float x) {
    return __fdividef(1.f, 1.f + __expf(-x));
}

// ---------------- stats helpers ----------------
__global__ void zero_stats_kernel() {
    int t = threadIdx.x;
    if (t < 192) { g_sumF[t] = 0.f; g_sumsqF[t] = 0.f; }
    if (t < 64) { g_sumM[t] = 0.0; g_sumsqM[t] = 0.0; }
}

__global__ void finalize_statsM_kernel(int count, int dim) {
    int d = threadIdx.x;
    if (d < dim) {
        double m = g_sumM[d] / (double)count;
        double v = g_sumsqM[d] / (double)count - m * m;
        g_meanM[d] = (float)m;
        g_rstdM[d] = (float)(1.0 / sqrt(v + 1e-5));
    }
    if (d < 64) { g_sumM[d] = 0.0; g_sumsqM[d] = 0.0; }
}

// ---------------- layer 0: row-major input, smem transpose, fast fused stats ----------------
__global__ __launch_bounds__(256) void layer0_kernel(
    const float* __restrict__ in,
    const float* __restrict__ Wm, const float* __restrict__ Wk,
    float* __restrict__ out, int N)
{
    __shared__ float xs[256][33];
    __shared__ ull wp[1024];
    __shared__ float rb[8][257];

    int tid = threadIdx.x;
    int lane = tid & 31, wid = tid >> 5;
    for (int t = tid; t < 1024; t += 256) wp[t] = pk2(Wm[t], Wk[t]);

    int n0 = blockIdx.x * 256;
    int npts = N - n0; if (npts > 256) npts = 256;
    for (int idx = tid; idx < npts * 32; idx += 256)
        xs[idx >> 5][idx & 31] = in[(size_t)n0 * 32 + idx];
    __syncthreads();

    int n = n0 + tid;
    bool valid = (tid < npts);

    ull acc[32];
#pragma unroll
    for (int d = 0; d < 32; d++) acc[d] = 0ull;

    if (valid) {
#pragma unroll
        for (int c = 0; c < 32; c++) {
            float z = xs[tid][c];
            ull zz = pk2(z, z);
            const ull* w = &wp[c * 32];
#pragma unroll
            for (int d = 0; d < 32; d++) acc[d] = ffma2(zz, w[d], acc[d]);
        }
#pragma unroll
        for (int d = 0; d < 32; d++) {
            float lo, hi; upk2(acc[d], lo, hi);
            out[(size_t)d * N + n] = lo;
            out[(size_t)(32 + d) * N + n] = hi;
        }
    }

    // stats: 8 rounds of 8 channels via smem transpose, one warp per channel
#pragma unroll
    for (int r = 0; r < 8; r++) {
        __syncthreads();
#pragma unroll
        for (int c8 = 0; c8 < 8; c8++) {
            int ch = r * 8 + c8;
            float v = 0.f;
            if (valid) {
                float lo, hi;
                if (ch < 32) { upk2(acc[ch], lo, hi); v = lo; }
                else         { upk2(acc[ch - 32], lo, hi); v = hi; }
            }
            rb[c8][tid] = v;
        }
        __syncthreads();
        {
            int ch = r * 8 + wid;
            float s = 0.f, q = 0.f;
#pragma unroll
            for (int j = 0; j < 8; j++) {
                float v = rb[wid][lane + 32 * j];
                s += v; q = fmaf(v, v, q);
            }
#pragma unroll
            for (int o = 16; o > 0; o >>= 1) {
                s += __shfl_down_sync(0xffffffffu, s, o);
                q += __shfl_down_sync(0xffffffffu, q, o);
            }
            if (lane == 0) {
                atomicAdd(&g_sumF[ch], s);
                atomicAdd(&g_sumsqF[ch], q);
            }
        }
    }
}

// ---------------- BN layer: one tower per blockIdx.y, smem-staged, fast stats ----------------
template <bool STATS>
__global__ __launch_bounds__(256) void layerBN2_kernel(
    const float* __restrict__ in,
    const float* __restrict__ W0, const float* __restrict__ W1,
    float* __restrict__ out, int N, int rs, int ws_stage)
{
    __shared__ float xs[32][258];
    __shared__ float ws[1024];
    __shared__ float sm[32], sr[32];
    __shared__ float rb[8][257];

    int tid = threadIdx.x;
    int lane = tid & 31, wid = tid >> 5;
    int t = blockIdx.y;
    int cb = t * 32;
    const float* W = t ? W1 : W0;
    for (int i = tid; i < 1024; i += 256) ws[i] = W[i];
    if (tid < 32) {
        double m = (double)g_sumF[rs * 64 + cb + tid] / (double)N;
        double v = (double)g_sumsqF[rs * 64 + cb + tid] / (double)N - m * m;
        sm[tid] = (float)m;
        sr[tid] = (float)(1.0 / sqrt(v + 1e-5));
    }

    int n0 = blockIdx.x * 256;
    if ((n0 + 256 <= N) && ((N & 3) == 0)) {
        for (int idx = tid; idx < 32 * 64; idx += 256) {
            int c = idx >> 6, p4 = (idx & 63) * 4;
            float4 v = *(const float4*)(in + (size_t)(cb + c) * N + n0 + p4);
            xs[c][p4] = v.x; xs[c][p4 + 1] = v.y; xs[c][p4 + 2] = v.z; xs[c][p4 + 3] = v.w;
        }
    } else {
        for (int idx = tid; idx < 32 * 256; idx += 256) {
            int c = idx >> 8, p = idx & 255;
            int n = n0 + p;
            xs[c][p] = (n < N) ? in[(size_t)(cb + c) * N + n] : 0.f;
        }
    }
    __syncthreads();

    int n = n0 + tid;
    bool valid = (n < N);

    float acc[32];
#pragma unroll
    for (int d = 0; d < 32; d++) acc[d] = 0.f;

#pragma unroll
    for (int c = 0; c < 32; c++) {
        float x = fmaxf((xs[c][tid] - sm[c]) * sr[c], 0.f);
        const float* w = &ws[c * 32];
#pragma unroll
        for (int d = 0; d < 32; d++) acc[d] = fmaf(x, w[d], acc[d]);
    }
    if (valid) {
#pragma unroll
        for (int d = 0; d < 32; d++) out[(size_t)(cb + d) * N + n] = acc[d];
    }

    if (STATS) {
#pragma unroll
        for (int r = 0; r < 4; r++) {
            __syncthreads();
#pragma unroll
            for (int c8 = 0; c8 < 8; c8++)
                rb[c8][tid] = valid ? acc[r * 8 + c8] : 0.f;
            __syncthreads();
            {
                int ch = r * 8 + wid;
                float s = 0.f, q = 0.f;
#pragma unroll
                for (int j = 0; j < 8; j++) {
                    float v = rb[wid][lane + 32 * j];
                    s += v; q = fmaf(v, v, q);
                }
#pragma unroll
                for (int o = 16; o > 0; o >>= 1) {
                    s += __shfl_down_sync(0xffffffffu, s, o);
                    q += __shfl_down_sync(0xffffffffu, q, o);
                }
                if (lane == 0) {
                    atomicAdd(&g_sumF[ws_stage * 64 + cb + ch], s);
                    atomicAdd(&g_sumsqF[ws_stage * 64 + cb + ch], q);
                }
            }
        }
    }
}

// ---------------- output layer: one tower per blockIdx.y ----------------
__global__ __launch_bounds__(256) void layerOut2_kernel(
    const float* __restrict__ in,
    const float* __restrict__ W0, const float* __restrict__ W1,
    const float* __restrict__ b0, const float* __restrict__ b1,
    float* __restrict__ o0, float* __restrict__ o1, int N, int rs)
{
    __shared__ float xs[32][258];
    __shared__ float ws[512];
    __shared__ float sm[32], sr[32];
    __shared__ float bb[16];

    int tid = threadIdx.x;
    int t = blockIdx.y;
    int cb = t * 32;
    const float* W = t ? W1 : W0;
    const float* bias = t ? b1 : b0;
    float* out = t ? o1 : o0;
    for (int i = tid; i < 512; i += 256) ws[i] = W[i];
    if (tid < 32) {
        double m = (double)g_sumF[rs * 64 + cb + tid] / (double)N;
        double v = (double)g_sumsqF[rs * 64 + cb + tid] / (double)N - m * m;
        sm[tid] = (float)m;
        sr[tid] = (float)(1.0 / sqrt(v + 1e-5));
    }
    if (tid < 16) bb[tid] = bias[tid];

    int n0 = blockIdx.x * 256;
    if ((n0 + 256 <= N) && ((N & 3) == 0)) {
        for (int idx = tid; idx < 32 * 64; idx += 256) {
            int c = idx >> 6, p4 = (idx & 63) * 4;
            float4 v = *(const float4*)(in + (size_t)(cb + c) * N + n0 + p4);
            xs[c][p4] = v.x; xs[c][p4 + 1] = v.y; xs[c][p4 + 2] = v.z; xs[c][p4 + 3] = v.w;
        }
    } else {
        for (int idx = tid; idx < 32 * 256; idx += 256) {
            int c = idx >> 8, p = idx & 255;
            int n = n0 + p;
            xs[c][p] = (n < N) ? in[(size_t)(cb + c) * N + n] : 0.f;
        }
    }
    __syncthreads();

    int n = n0 + tid;
    if (n >= N) return;

    float acc[16];
#pragma unroll
    for (int d = 0; d < 16; d++) acc[d] = bb[d];

#pragma unroll
    for (int c = 0; c < 32; c++) {
        float x = fmaxf((xs[c][tid] - sm[c]) * sr[c], 0.f);
        const float* w = &ws[c * 16];
#pragma unroll
        for (int d = 0; d < 16; d++) acc[d] = fmaf(x, w[d], acc[d]);
    }
#pragma unroll
    for (int d = 0; d < 16; d++) out[(size_t)d * N + n] = acc[d];
}

// ---------------- merge-branch layer ----------------
template <int DIN, int DOUT, bool BN, bool STATS, bool BIAS>
__global__ __launch_bounds__(256) void layerM_kernel(
    const float* __restrict__ in, const float* __restrict__ W,
    const float* __restrict__ bias, float* __restrict__ out, int N)
{
    __shared__ float Ws[DIN * DOUT];
    __shared__ float sb[DOUT];
    __shared__ float sm[DIN], sr[DIN];
    __shared__ double bs[DOUT], bq[DOUT];

    for (int t = threadIdx.x; t < DIN * DOUT; t += blockDim.x) Ws[t] = W[t];
    if (threadIdx.x < DOUT) sb[threadIdx.x] = BIAS ? bias[threadIdx.x] : 0.f;
    if (BN && threadIdx.x < DIN) {
        sm[threadIdx.x] = g_meanM[threadIdx.x];
        sr[threadIdx.x] = g_rstdM[threadIdx.x];
    }
    if (STATS && threadIdx.x < DOUT) { bs[threadIdx.x] = 0.0; bq[threadIdx.x] = 0.0; }
    __syncthreads();

    int n = blockIdx.x * blockDim.x + threadIdx.x;
    bool valid = (n < N);
    float acc[DOUT];
#pragma unroll
    for (int d = 0; d < DOUT; d++) acc[d] = sb[d];

    if (valid) {
#pragma unroll
        for (int c = 0; c < DIN; c++) {
            float xv = in[(size_t)n * DIN + c];
            if (BN) xv = fmaxf((xv - sm[c]) * sr[c], 0.f);
#pragma unroll
            for (int d = 0; d < DOUT; d++) acc[d] = fmaf(xv, Ws[c * DOUT + d], acc[d]);
        }
#pragma unroll
        for (int d = 0; d < DOUT; d++) out[(size_t)n * DOUT + d] = acc[d];
    }

    if (STATS) {
#pragma unroll
        for (int d = 0; d < DOUT; d++) {
            float v = valid ? acc[d] : 0.f;
            float v2 = v * v;
#pragma unroll
            for (int o = 16; o > 0; o >>= 1) {
                v  += __shfl_down_sync(0xffffffffu, v, o);
                v2 += __shfl_down_sync(0xffffffffu, v2, o);
            }
            if ((threadIdx.x & 31) == 0) {
                atomicAdd(&bs[d], (double)v);
                atomicAdd(&bq[d], (double)v2);
            }
        }
        __syncthreads();
        if (threadIdx.x < DOUT) {
            atomicAdd(&g_sumM[threadIdx.x], bs[threadIdx.x]);
            atomicAdd(&g_sumsqM[threadIdx.x], bq[threadIdx.x]);
        }
    }
}

// ---------------- batch ranges ----------------
__global__ void batch_ranges_kernel(const int* __restrict__ bidx, int N) {
    int n = blockIdx.x * blockDim.x + threadIdx.x;
    if (n >= N) return;
    int b = bidx[n];
    int pb = (n == 0) ? -1 : bidx[n - 1];
    for (int x = pb + 1; x <= b; x++) g_bstart[x] = n;
    if (n == N - 1) for (int x = b + 1; x <= 4; x++) g_bstart[x] = N;
}

// ---------------- NMS (eager, R6-style) + x smem cache + bbox early-out ----------------
__global__ __launch_bounds__(1024) void nms_kernel(
    const float* __restrict__ heat, const float* __restrict__ coords, int N)
{
    extern __shared__ float dynsh[];
    __shared__ float wv[32];
    __shared__ int   wix[32];
    __shared__ float scx, scy, scz;

    int b = blockIdx.x, tid = threadIdx.x;
    int s0 = g_bstart[b], s1 = g_bstart[b + 1];
    int cnt = s1 - s0;
    bool inS = (cnt <= NMS_SMEM_N);
    float* sl = inS ? dynsh : (g_s + (size_t)b * MAXN);
    float* xl = dynsh + NMS_SMEM_N;   // only valid when inS

    float bv = -INFINITY; int bi = 0;
    for (int l = tid; l < cnt; l += 1024) {
        int n = s0 + l;
        float v = heat[n];
        sl[l] = v;
        if (inS) xl[l] = coords[(size_t)n * 3];
        if (v > bv) { bv = v; bi = n; }
    }

    for (int k = 0; ; k++) {
#pragma unroll
        for (int o = 16; o > 0; o >>= 1) {
            float ov = __shfl_down_sync(0xffffffffu, bv, o);
            int   oi = __shfl_down_sync(0xffffffffu, bi, o);
            if (ov > bv || (ov == bv && oi < bi)) { bv = ov; bi = oi; }
        }
        if ((tid & 31) == 0) { wv[tid >> 5] = bv; wix[tid >> 5] = bi; }
        __syncthreads();
        if (tid < 32) {
            bv = wv[tid]; bi = wix[tid];
#pragma unroll
            for (int o = 16; o > 0; o >>= 1) {
                float ov = __shfl_down_sync(0xffffffffu, bv, o);
                int   oi = __shfl_down_sync(0xffffffffu, bi, o);
                if (ov > bv || (ov == bv && oi < bi)) { bv = ov; bi = oi; }
            }
            if (tid == 0) {
                g_topk[b * 32 + k] = bi;
                scx = coords[(size_t)bi * 3];
                scy = coords[(size_t)bi * 3 + 1];
                scz = coords[(size_t)bi * 3 + 2];
            }
        }
        __syncthreads();
        if (k == 31) break;

        float cx = scx, cy = scy, cz = scz;
        // eager fused suppress + argmax scan; bbox-x early-out (exact:
        // dx^2 >= 0.09 implies d2 >= 0.09 under rn-add of non-negatives)
        bv = -INFINITY; bi = 0;
        for (int l = tid; l < cnt; l += 1024) {
            float v = sl[l];
            int n = s0 + l;
            if (v != -INFINITY) {
                float xv = inS ? xl[l] : coords[(size_t)n * 3];
                float dx = __fadd_rn(xv, -cx);
                if (__fmul_rn(dx, dx) < 0.09f) {
                    float dy = __fadd_rn(coords[(size_t)n * 3 + 1], -cy);
                    float dz = __fadd_rn(coords[(size_t)n * 3 + 2], -cz);
                    float d2 = __fadd_rn(__fadd_rn(__fmul_rn(dx, dx), __fmul_rn(dy, dy)),
                                         __fmul_rn(dz, dz));
                    if (d2 < 0.09f) { v = -INFINITY; sl[l] = v; }
                }
            }
            if (v > bv || (v == bv && n < bi)) { bv = v; bi = n; }
        }
        // no extra sync: each warp rewrites only its own wv/wix slot next
        // iteration, and warp0 consumed them before the __syncthreads above.
    }
}

// ---------------- gather selected candidates ----------------
__global__ void gather_kernel(const float* __restrict__ coords, const int* __restrict__ bidx, int N) {
    int i = threadIdx.x;
    int idx = g_topk[i];
    float c0 = coords[idx * 3], c1 = coords[idx * 3 + 1], c2 = coords[idx * 3 + 2];
    g_ctr[i * 3] = c0; g_ctr[i * 3 + 1] = c1; g_ctr[i * 3 + 2] = c2;
    g_cb[i] = bidx[idx];
    for (int c = 0; c < 16; c++) {
        float kf = g_kern_feats[(size_t)c * N + idx];
        float mf = g_mask_feats[(size_t)c * N + idx];
        g_ck[i * 16 + c] = kf;
        g_feat[i * 35 + c] = kf;
        g_feat[i * 35 + 16 + c] = mf;
    }
    g_feat[i * 35 + 32] = c0;
    g_feat[i * 35 + 33] = c1;
    g_feat[i * 35 + 34] = c2;
}

// ---------------- weight generator ----------------
__global__ void weights_kernel(const float* __restrict__ Wwg, const float* __restrict__ bwg) {
    int i = blockIdx.x, j = threadIdx.x;
    if (j >= 337) return;
    float a = bwg[j];
#pragma unroll
    for (int c = 0; c < 16; c++) a = fmaf(g_ck[i * 16 + c], Wwg[c * 337 + j], a);
    g_weights[i * 337 + j] = a;
}

__global__ void beff_kernel() {
    int i = blockIdx.x, h = threadIdx.x;
    const float* wi = g_weights + i * 337;
    float b = wi[304 + h];
#pragma unroll
    for (int p = 0; p < 3; p++) b -= g_ctr[i * 3 + p] * wi[(16 + p) * 16 + h];
    g_beff[i * 16 + h] = b;
}

// ---------------- dynamic-conv masks: 256-point tiles ----------------
__global__ __launch_bounds__(256) void masks_kernel(
    const float* __restrict__ coords, float* __restrict__ out, int N, int outw)
{
    extern __shared__ float dyn[];
    float* zs = dyn;                    // [19][MTILE+2]
    float* ot = dyn + 19 * (MTILE + 2); // [32][MTILE+1]

    int i_base = blockIdx.y * 32;
    int n0 = blockIdx.x * MTILE;
    int tid = threadIdx.x;
    int i_local = tid >> 3;
    int hg = tid & 7;
    int i = i_base + i_local;
    int h0 = hg * 2;

    const float* wi = g_weights + i * 337;
    ull w0[19], w1[19];
#pragma unroll
    for (int r = 0; r < 19; r++) {
        float a = wi[r * 16 + h0], b = wi[r * 16 + h0 + 1];
        w0[r] = pk2(a, a);
        w1[r] = pk2(b, b);
    }
    float be0f = g_beff[i * 16 + h0], be1f = g_beff[i * 16 + h0 + 1];
    ull be0 = pk2(be0f, be0f), be1 = pk2(be1f, be1f);
    float w2a = wi[320 + h0], w2b = wi[320 + h0 + 1];
    float b2 = wi[336];

    for (int idx = tid; idx < 16 * MTILE; idx += 256) {
        int c = idx >> 8, p = idx & (MTILE - 1);
        int n = n0 + p;
        zs[c * (MTILE + 2) + p] = (n < N) ? g_mask_feats[(size_t)c * N + n] : 0.f;
    }
    for (int idx = tid; idx < MTILE * 3; idx += 256) {
        int p = idx / 3, c = idx % 3;
        int n = n0 + p;
        zs[(16 + c) * (MTILE + 2) + p] = (n < N) ? coords[(size_t)n * 3 + c] : 0.f;
    }
    __syncthreads();

#pragma unroll 2
    for (int pp = 0; pp < MTILE / 2; pp++) {
        ull a0 = be0, a1 = be1;
#pragma unroll
        for (int r = 0; r < 19; r++) {
            ull z = *(const ull*)&zs[r * (MTILE + 2) + pp * 2];
            a0 = ffma2(z, w0[r], a0);
            a1 = ffma2(z, w1[r], a1);
        }
        float a0l, a0h, a1l, a1h;
        upk2(a0, a0l, a0h);
        upk2(a1, a1l, a1h);
        float pl = fmaf(fmaxf(a0l, 0.f), w2a, fmaxf(a1l, 0.f) * w2b);
        float ph = fmaf(fmaxf(a0h, 0.f), w2a, fmaxf(a1h, 0.f) * w2b);
        pl += __shfl_down_sync(0xffffffffu, pl, 4, 8);
        ph += __shfl_down_sync(0xffffffffu, ph, 4, 8);
        pl += __shfl_down_sync(0xffffffffu, pl, 2, 8);
        ph += __shfl_down_sync(0xffffffffu, ph, 2, 8);
        pl += __shfl_down_sync(0xffffffffu, pl, 1, 8);
        ph += __shfl_down_sync(0xffffffffu, ph, 1, 8);
        if (hg == 0) {
            ot[i_local * (MTILE + 1) + pp * 2]     = fast_sigmoid(pl + b2);
            ot[i_local * (MTILE + 1) + pp * 2 + 1] = fast_sigmoid(ph + b2);
        }
    }
    __syncthreads();

    for (int idx = tid; idx < 32 * MTILE; idx += 256) {
        int il = idx >> 8, p = idx & (MTILE - 1);
        int n = n0 + p;
        if (n < N) out[(size_t)(i_base + il) * outw + n] = ot[il * (MTILE + 1) + p];
    }
}

// ---------------- merge branch ----------------
__global__ void diff_kernel() {
    int p = blockIdx.x * blockDim.x + threadIdx.x;
    if (p >= I_CNT * I_CNT) return;
    int i = p >> 7, j = p & 127;
#pragma unroll
    for (int c = 0; c < 35; c++)
        g_pairA[(size_t)p * 35 + c] = fmaxf(fabsf(g_feat[i * 35 + c] - g_feat[j * 35 + c]), 1e-6f);
}

__global__ void merge_out_kernel(const float* __restrict__ WgOut, const float* __restrict__ bg,
                                 float* __restrict__ out, int N, int outw) {
    int p = blockIdx.x * blockDim.x + threadIdx.x;
    if (p >= I_CNT * I_CNT) return;
    int i = p >> 7, j = p & 127;
    float a = bg[0];
#pragma unroll
    for (int c = 0; c < 35; c++) {
        float xv = g_pairB[(size_t)p * 35 + c];
        xv = fmaxf((xv - g_meanM[c]) * g_rstdM[c], 0.f);
        a = fmaf(xv, WgOut[c], a);
    }
    float m = (g_cb[i] != g_cb[j]) ? 0.f : fast_sigmoid(a);
    out[(size_t)i * outw + N + j] = m;
}

// ---------------- launcher ----------------
extern "C" void kernel_launch(void* const* d_in, const int* in_sizes, int n_in,
                              void* d_out, int out_size)
{
    const float* output_feats = (const float*)d_in[0];
    const float* coords       = (const float*)d_in[1];
    const float* heat         = (const float*)d_in[2];
    const int*   batch_idxs   = (const int*)d_in[3];
    const float* Wm     = (const float*)d_in[4];
    const float* Wm_out = (const float*)d_in[5];
    const float* bm_out = (const float*)d_in[6];
    const float* Wk     = (const float*)d_in[7];
    const float* Wk_out = (const float*)d_in[8];
    const float* bk_out = (const float*)d_in[9];
    const float* Wg     = (const float*)d_in[10];
    const float* Wg_out = (const float*)d_in[11];
    const float* bg_out = (const float*)d_in[12];
    const float* Wwg    = (const float*)d_in[13];
    const float* bwg    = (const float*)d_in[14];
    float* out = (float*)d_out;

    int N = in_sizes[2];
    int outw = N + I_CNT;
    int nb = (N + 255) / 256;

    float *tA, *tB, *maskf, *kernf, *pairA, *pairB;
    cudaGetSymbolAddress((void**)&tA,    g_tA);
    cudaGetSymbolAddress((void**)&tB,    g_tB);
    cudaGetSymbolAddress((void**)&maskf, g_mask_feats);
    cudaGetSymbolAddress((void**)&kernf, g_kern_feats);
    cudaGetSymbolAddress((void**)&pairA, g_pairA);
    cudaGetSymbolAddress((void**)&pairB, g_pairB);

    const int MASK_SMEM = (19 * (MTILE + 2) + 32 * (MTILE + 1)) * (int)sizeof(float);
    const int NMS_SMEM = 2 * NMS_SMEM_N * (int)sizeof(float);

    static cudaStream_t s1;
    static cudaEvent_t evFork1, evJoin1, evFork2, evJoin2;
    static bool init_done = false;
    if (!init_done) {
        cudaFuncSetAttribute(nms_kernel, cudaFuncAttributeMaxDynamicSharedMemorySize,
                             NMS_SMEM);
        cudaFuncSetAttribute(masks_kernel, cudaFuncAttributeMaxDynamicSharedMemorySize,
                             MASK_SMEM);
        cudaStreamCreateWithFlags(&s1, cudaStreamNonBlocking);
        cudaEventCreateWithFlags(&evFork1, cudaEventDisableTiming);
        cudaEventCreateWithFlags(&evJoin1, cudaEventDisableTiming);
        cudaEventCreateWithFlags(&evFork2, cudaEventDisableTiming);
        cudaEventCreateWithFlags(&evJoin2, cudaEventDisableTiming);
        init_done = true;
    }

    batch_ranges_kernel<<<nb, 256>>>(batch_idxs, N);

    cudaEventRecord(evFork1, 0);
    cudaStreamWaitEvent(s1, evFork1, 0);
    nms_kernel<<<4, 1024, NMS_SMEM, s1>>>(heat, coords, N);
    cudaEventRecord(evJoin1, s1);

    zero_stats_kernel<<<1, 192>>>();

    // tower chain: fused stats, no finalize launches (consumers read raw sums)
    dim3 g2(nb, 2);
    layer0_kernel<<<nb, 256>>>(output_feats, Wm, Wk, tA, N);
    layerBN2_kernel<true><<<g2, 256>>>(tA, Wm + 1024, Wk + 1024, tB, N, 0, 1);
    layerBN2_kernel<true><<<g2, 256>>>(tB, Wm + 2048, Wk + 2048, tA, N, 1, 2);
    layerOut2_kernel<<<g2, 256>>>(tA, Wm_out, Wk_out, bm_out, bk_out, maskf, kernf, N, 2);

    cudaStreamWaitEvent(0, evJoin1, 0);
    gather_kernel<<<1, 128>>>(coords, batch_idxs, N);
    weights_kernel<<<128, 352>>>(Wwg, bwg);

    cudaEventRecord(evFork2, 0);
    cudaStreamWaitEvent(s1, evFork2, 0);
    diff_kernel<<<64, 256, 0, s1>>>();
    layerM_kernel<35, 35, false, true, false><<<64, 256, 0, s1>>>(pairA, Wg,        nullptr, pairB, I_CNT * I_CNT);
    finalize_statsM_kernel<<<1, 64, 0, s1>>>(I_CNT * I_CNT, 35);
    layerM_kernel<35, 35, true,  true, false><<<64, 256, 0, s1>>>(pairB, Wg + 1225, nullptr, pairA, I_CNT * I_CNT);
    finalize_statsM_kernel<<<1, 64, 0, s1>>>(I_CNT * I_CNT, 35);
    layerM_kernel<35, 35, true,  true, false><<<64, 256, 0, s1>>>(pairA, Wg + 2450, nullptr, pairB, I_CNT * I_CNT);
    finalize_statsM_kernel<<<1, 64, 0, s1>>>(I_CNT * I_CNT, 35);
    merge_out_kernel<<<64, 256, 0, s1>>>(Wg_out, bg_out, out, N, outw);
    cudaEventRecord(evJoin2, s1);

    beff_kernel<<<128, 16>>>();
    dim3 mg((N + MTILE - 1) / MTILE, 4);
    masks_kernel<<<mg, 256, MASK_SMEM>>>(coords, out, N, outw);

    cudaStreamWaitEvent(0, evJoin2, 0);
}

// round 11
// speedup vs baseline: 1.2677x; 1.0728x over previous
#include <cuda_runtime.h>
#include <math.h>

#define MAXN 100000
#define I_CNT 128
#define NMS_SMEM_N 28000
#define MTILE 256

typedef unsigned long long ull;

// ---------------- device scratch (no allocations allowed) ----------------
__device__ float g_tA[64 * MAXN];          // transposed activations [64][N]
__device__ float g_tB[64 * MAXN];
__device__ float g_mask_feats[16 * MAXN];  // transposed [16][N]
__device__ float g_kern_feats[16 * MAXN];  // transposed [16][N]
__device__ float g_s[4 * MAXN];            // nms fallback only
__device__ int   g_bstart[8];
__device__ int   g_topk[I_CNT];
__device__ float g_ctr[I_CNT * 3];
__device__ int   g_cb[I_CNT];
__device__ float g_weights[I_CNT * 337];
__device__ float g_beff[I_CNT * 16];
__device__ float g_feat[I_CNT * 35];
__device__ float g_pairA[I_CNT * I_CNT * 35];
__device__ float g_pairB[I_CNT * I_CNT * 35];
__device__ float g_sumF[3 * 64];           // staged tower stats (float)
__device__ float g_sumsqF[3 * 64];
__device__ double g_sumM[3 * 64];          // staged merge stats (double)
__device__ double g_sumsqM[3 * 64];

// ---------------- f32x2 helpers ----------------
__device__ __forceinline__ ull pk2(float lo, float hi) {
    ull r; asm("mov.b64 %0, {%1, %2};" : "=l"(r) : "f"(lo), "f"(hi)); return r;
}
__device__ __forceinline__ void upk2(ull v, float& lo, float& hi) {
    asm("mov.b64 {%0, %1}, %2;" : "=f"(lo), "=f"(hi) : "l"(v));
}
__device__ __forceinline__ ull ffma2(ull a, ull b, ull c) {
    ull d; asm("fma.rn.f32x2 %0, %1, %2, %3;" : "=l"(d) : "l"(a), "l"(b), "l"(c)); return d;
}
__device__ __forceinline__ float fast_sigmoid(float x) {
    return __fdividef(1.f, 1.f + __expf(-x));
}

// ---------------- prologue: batch ranges + zero all stats ----------------
__global__ void prologue_kernel(const int* __restrict__ bidx, int N) {
    int n = blockIdx.x * 256 + threadIdx.x;
    if (blockIdx.x == 0 && threadIdx.x < 192) {
        g_sumF[threadIdx.x] = 0.f; g_sumsqF[threadIdx.x] = 0.f;
        g_sumM[threadIdx.x] = 0.0; g_sumsqM[threadIdx.x] = 0.0;
    }
    if (n >= N) return;
    int b = bidx[n];
    int pb = (n == 0) ? -1 : bidx[n - 1];
    for (int x = pb + 1; x <= b; x++) g_bstart[x] = n;
    if (n == N - 1) for (int x = b + 1; x <= 4; x++) g_bstart[x] = N;
}

// ---------------- layer 0: row-major input, smem transpose, fused stats ----------------
__global__ __launch_bounds__(256) void layer0_kernel(
    const float* __restrict__ in,
    const float* __restrict__ Wm, const float* __restrict__ Wk,
    float* __restrict__ out, int N)
{
    __shared__ float xs[256][33];
    __shared__ ull wp[1024];
    __shared__ float rb[8][257];

    int tid = threadIdx.x;
    int lane = tid & 31, wid = tid >> 5;
    for (int t = tid; t < 1024; t += 256) wp[t] = pk2(Wm[t], Wk[t]);

    int n0 = blockIdx.x * 256;
    int npts = N - n0; if (npts > 256) npts = 256;
    for (int idx = tid; idx < npts * 32; idx += 256)
        xs[idx >> 5][idx & 31] = in[(size_t)n0 * 32 + idx];
    __syncthreads();

    int n = n0 + tid;
    bool valid = (tid < npts);

    ull acc[32];
#pragma unroll
    for (int d = 0; d < 32; d++) acc[d] = 0ull;

    if (valid) {
#pragma unroll
        for (int c = 0; c < 32; c++) {
            float z = xs[tid][c];
            ull zz = pk2(z, z);
            const ull* w = &wp[c * 32];
#pragma unroll
            for (int d = 0; d < 32; d++) acc[d] = ffma2(zz, w[d], acc[d]);
        }
#pragma unroll
        for (int d = 0; d < 32; d++) {
            float lo, hi; upk2(acc[d], lo, hi);
            out[(size_t)d * N + n] = lo;
            out[(size_t)(32 + d) * N + n] = hi;
        }
    }

#pragma unroll
    for (int r = 0; r < 8; r++) {
        __syncthreads();
#pragma unroll
        for (int c8 = 0; c8 < 8; c8++) {
            int ch = r * 8 + c8;
            float v = 0.f;
            if (valid) {
                float lo, hi;
                if (ch < 32) { upk2(acc[ch], lo, hi); v = lo; }
                else         { upk2(acc[ch - 32], lo, hi); v = hi; }
            }
            rb[c8][tid] = v;
        }
        __syncthreads();
        {
            int ch = r * 8 + wid;
            float s = 0.f, q = 0.f;
#pragma unroll
            for (int j = 0; j < 8; j++) {
                float v = rb[wid][lane + 32 * j];
                s += v; q = fmaf(v, v, q);
            }
#pragma unroll
            for (int o = 16; o > 0; o >>= 1) {
                s += __shfl_down_sync(0xffffffffu, s, o);
                q += __shfl_down_sync(0xffffffffu, q, o);
            }
            if (lane == 0) {
                atomicAdd(&g_sumF[ch], s);
                atomicAdd(&g_sumsqF[ch], q);
            }
        }
    }
}

// ---------------- BN layer v3: 2 points per thread (f32x2), one tower per blockIdx.y ----------------
// dynamic smem layout: wp[1024] ull | smA[32] ull | smB[32] ull | xs[32*516] float (rb aliases xs)
#define BN3_SMEM (1024 * 8 + 32 * 8 + 32 * 8 + 32 * 516 * 4)
template <bool STATS>
__global__ __launch_bounds__(256) void layerBN3_kernel(
    const float* __restrict__ in,
    const float* __restrict__ W0, const float* __restrict__ W1,
    float* __restrict__ out, int N, int rs, int ws_stage)
{
    extern __shared__ char dynraw[];
    ull* wp = (ull*)dynraw;
    ull* smA = wp + 1024;
    ull* smB = smA + 32;
    float* xs = (float*)(smB + 32);
    float* rb = xs;   // reused for stats staging

    int tid = threadIdx.x;
    int lane = tid & 31, wid = tid >> 5;
    int t = blockIdx.y;
    int cb = t * 32;
    const float* W = t ? W1 : W0;
    for (int i = tid; i < 1024; i += 256) { float w = W[i]; wp[i] = pk2(w, w); }
    if (tid < 32) {
        double m = (double)g_sumF[rs * 64 + cb + tid] / (double)N;
        double v = (double)g_sumsqF[rs * 64 + cb + tid] / (double)N - m * m;
        float sr = (float)(1.0 / sqrt(v + 1e-5));
        float sb = (float)(-m) * sr;
        smA[tid] = pk2(sr, sr);
        smB[tid] = pk2(sb, sb);
    }

    int n0 = blockIdx.x * 512;
    if ((n0 + 512 <= N) && ((N & 3) == 0)) {
        for (int idx = tid; idx < 32 * 128; idx += 256) {
            int c = idx >> 7, p4 = (idx & 127) * 4;
            float4 v = *(const float4*)(in + (size_t)(cb + c) * N + n0 + p4);
            float* xr = xs + c * 516 + p4;
            xr[0] = v.x; xr[1] = v.y; xr[2] = v.z; xr[3] = v.w;
        }
    } else {
        for (int idx = tid; idx < 32 * 512; idx += 256) {
            int c = idx >> 9, p = idx & 511;
            int n = n0 + p;
            xs[c * 516 + p] = (n < N) ? in[(size_t)(cb + c) * N + n] : 0.f;
        }
    }
    __syncthreads();

    int n = n0 + 2 * tid;
    bool v0 = (n < N), v1 = (n + 1 < N);
    bool vec = ((N & 1) == 0) && v1;

    ull acc[32];
#pragma unroll
    for (int d = 0; d < 32; d++) acc[d] = 0ull;

#pragma unroll 4
    for (int c = 0; c < 32; c++) {
        ull z = *(const ull*)&xs[c * 516 + 2 * tid];
        ull zb = ffma2(z, smA[c], smB[c]);
        float lo, hi; upk2(zb, lo, hi);
        ull x2 = pk2(fmaxf(lo, 0.f), fmaxf(hi, 0.f));
        const ull* w = &wp[c * 32];
#pragma unroll
        for (int d = 0; d < 32; d++) acc[d] = ffma2(x2, w[d], acc[d]);
    }

    if (vec) {
#pragma unroll
        for (int d = 0; d < 32; d++) {
            float lo, hi; upk2(acc[d], lo, hi);
            *(float2*)(out + (size_t)(cb + d) * N + n) = make_float2(lo, hi);
        }
    } else if (v0) {
#pragma unroll
        for (int d = 0; d < 32; d++) {
            float lo, hi; upk2(acc[d], lo, hi);
            out[(size_t)(cb + d) * N + n] = lo;
            if (v1) out[(size_t)(cb + d) * N + n + 1] = hi;
        }
    }

    if (STATS) {
#pragma unroll
        for (int r = 0; r < 4; r++) {
            __syncthreads();
#pragma unroll
            for (int c8 = 0; c8 < 8; c8++) {
                float lo, hi; upk2(acc[r * 8 + c8], lo, hi);
                float* rr = rb + c8 * 516 + 2 * tid;
                rr[0] = v0 ? lo : 0.f;
                rr[1] = v1 ? hi : 0.f;
            }
            __syncthreads();
            {
                int ch = r * 8 + wid;
                float s = 0.f, q = 0.f;
#pragma unroll
                for (int j = 0; j < 16; j++) {
                    float v = rb[wid * 516 + lane + 32 * j];
                    s += v; q = fmaf(v, v, q);
                }
#pragma unroll
                for (int o = 16; o > 0; o >>= 1) {
                    s += __shfl_down_sync(0xffffffffu, s, o);
                    q += __shfl_down_sync(0xffffffffu, q, o);
                }
                if (lane == 0) {
                    atomicAdd(&g_sumF[ws_stage * 64 + cb + ch], s);
                    atomicAdd(&g_sumsqF[ws_stage * 64 + cb + ch], q);
                }
            }
        }
    }
}

// ---------------- output layer v3: 2 points per thread, one tower per blockIdx.y ----------------
// dynamic smem: wp[512] ull | smA[32] | smB[32] | bb[16] ull | xs[32*516] float
#define OUT3_SMEM (512 * 8 + 32 * 8 + 32 * 8 + 16 * 8 + 32 * 516 * 4)
__global__ __launch_bounds__(256) void layerOut3_kernel(
    const float* __restrict__ in,
    const float* __restrict__ W0, const float* __restrict__ W1,
    const float* __restrict__ b0, const float* __restrict__ b1,
    float* __restrict__ o0, float* __restrict__ o1, int N, int rs)
{
    extern __shared__ char dynraw[];
    ull* wp = (ull*)dynraw;
    ull* smA = wp + 512;
    ull* smB = smA + 32;
    ull* bb = smB + 32;
    float* xs = (float*)(bb + 16);

    int tid = threadIdx.x;
    int t = blockIdx.y;
    int cb = t * 32;
    const float* W = t ? W1 : W0;
    const float* bias = t ? b1 : b0;
    float* out = t ? o1 : o0;
    for (int i = tid; i < 512; i += 256) { float w = W[i]; wp[i] = pk2(w, w); }
    if (tid < 32) {
        double m = (double)g_sumF[rs * 64 + cb + tid] / (double)N;
        double v = (double)g_sumsqF[rs * 64 + cb + tid] / (double)N - m * m;
        float sr = (float)(1.0 / sqrt(v + 1e-5));
        float sb = (float)(-m) * sr;
        smA[tid] = pk2(sr, sr);
        smB[tid] = pk2(sb, sb);
    }
    if (tid < 16) { float b = bias[tid]; bb[tid] = pk2(b, b); }

    int n0 = blockIdx.x * 512;
    if ((n0 + 512 <= N) && ((N & 3) == 0)) {
        for (int idx = tid; idx < 32 * 128; idx += 256) {
            int c = idx >> 7, p4 = (idx & 127) * 4;
            float4 v = *(const float4*)(in + (size_t)(cb + c) * N + n0 + p4);
            float* xr = xs + c * 516 + p4;
            xr[0] = v.x; xr[1] = v.y; xr[2] = v.z; xr[3] = v.w;
        }
    } else {
        for (int idx = tid; idx < 32 * 512; idx += 256) {
            int c = idx >> 9, p = idx & 511;
            int n = n0 + p;
            xs[c * 516 + p] = (n < N) ? in[(size_t)(cb + c) * N + n] : 0.f;
        }
    }
    __syncthreads();

    int n = n0 + 2 * tid;
    bool v0 = (n < N), v1 = (n + 1 < N);
    bool vec = ((N & 1) == 0) && v1;

    ull acc[16];
#pragma unroll
    for (int d = 0; d < 16; d++) acc[d] = bb[d];

#pragma unroll 4
    for (int c = 0; c < 32; c++) {
        ull z = *(const ull*)&xs[c * 516 + 2 * tid];
        ull zb = ffma2(z, smA[c], smB[c]);
        float lo, hi; upk2(zb, lo, hi);
        ull x2 = pk2(fmaxf(lo, 0.f), fmaxf(hi, 0.f));
        const ull* w = &wp[c * 16];
#pragma unroll
        for (int d = 0; d < 16; d++) acc[d] = ffma2(x2, w[d], acc[d]);
    }

    if (vec) {
#pragma unroll
        for (int d = 0; d < 16; d++) {
            float lo, hi; upk2(acc[d], lo, hi);
            *(float2*)(out + (size_t)d * N + n) = make_float2(lo, hi);
        }
    } else if (v0) {
#pragma unroll
        for (int d = 0; d < 16; d++) {
            float lo, hi; upk2(acc[d], lo, hi);
            out[(size_t)d * N + n] = lo;
            if (v1) out[(size_t)d * N + n + 1] = hi;
        }
    }
}

// ---------------- NMS (eager) + x smem cache + bbox early-out ----------------
__global__ __launch_bounds__(1024) void nms_kernel(
    const float* __restrict__ heat, const float* __restrict__ coords, int N)
{
    extern __shared__ float dynsh[];
    __shared__ float wv[32];
    __shared__ int   wix[32];
    __shared__ float scx, scy, scz;

    int b = blockIdx.x, tid = threadIdx.x;
    int s0 = g_bstart[b], s1 = g_bstart[b + 1];
    int cnt = s1 - s0;
    bool inS = (cnt <= NMS_SMEM_N);
    float* sl = inS ? dynsh : (g_s + (size_t)b * MAXN);
    float* xl = dynsh + NMS_SMEM_N;

    float bv = -INFINITY; int bi = 0;
    for (int l = tid; l < cnt; l += 1024) {
        int n = s0 + l;
        float v = heat[n];
        sl[l] = v;
        if (inS) xl[l] = coords[(size_t)n * 3];
        if (v > bv) { bv = v; bi = n; }
    }

    for (int k = 0; ; k++) {
#pragma unroll
        for (int o = 16; o > 0; o >>= 1) {
            float ov = __shfl_down_sync(0xffffffffu, bv, o);
            int   oi = __shfl_down_sync(0xffffffffu, bi, o);
            if (ov > bv || (ov == bv && oi < bi)) { bv = ov; bi = oi; }
        }
        if ((tid & 31) == 0) { wv[tid >> 5] = bv; wix[tid >> 5] = bi; }
        __syncthreads();
        if (tid < 32) {
            bv = wv[tid]; bi = wix[tid];
#pragma unroll
            for (int o = 16; o > 0; o >>= 1) {
                float ov = __shfl_down_sync(0xffffffffu, bv, o);
                int   oi = __shfl_down_sync(0xffffffffu, bi, o);
                if (ov > bv || (ov == bv && oi < bi)) { bv = ov; bi = oi; }
            }
            if (tid == 0) {
                g_topk[b * 32 + k] = bi;
                scx = coords[(size_t)bi * 3];
                scy = coords[(size_t)bi * 3 + 1];
                scz = coords[(size_t)bi * 3 + 2];
            }
        }
        __syncthreads();
        if (k == 31) break;

        float cx = scx, cy = scy, cz = scz;
        bv = -INFINITY; bi = 0;
        for (int l = tid; l < cnt; l += 1024) {
            float v = sl[l];
            int n = s0 + l;
            if (v != -INFINITY) {
                float xv = inS ? xl[l] : coords[(size_t)n * 3];
                float dx = __fadd_rn(xv, -cx);
                if (__fmul_rn(dx, dx) < 0.09f) {
                    float dy = __fadd_rn(coords[(size_t)n * 3 + 1], -cy);
                    float dz = __fadd_rn(coords[(size_t)n * 3 + 2], -cz);
                    float d2 = __fadd_rn(__fadd_rn(__fmul_rn(dx, dx), __fmul_rn(dy, dy)),
                                         __fmul_rn(dz, dz));
                    if (d2 < 0.09f) { v = -INFINITY; sl[l] = v; }
                }
            }
            if (v > bv || (v == bv && n < bi)) { bv = v; bi = n; }
        }
    }
}

// ---------------- fused gather + weight-gen + beff: one block per instance ----------------
__global__ __launch_bounds__(352) void gwb_kernel(
    const float* __restrict__ coords, const int* __restrict__ bidx,
    const float* __restrict__ Wwg, const float* __restrict__ bwg, int N)
{
    __shared__ float cks[16];
    __shared__ float ctrs[3];
    __shared__ float wrow[352];
    int i = blockIdx.x, j = threadIdx.x;
    int idx = g_topk[i];
    if (j < 16) {
        float kf = g_kern_feats[(size_t)j * N + idx];
        float mf = g_mask_feats[(size_t)j * N + idx];
        cks[j] = kf;
        g_feat[i * 35 + j] = kf;
        g_feat[i * 35 + 16 + j] = mf;
    }
    if (j >= 16 && j < 19) {
        float c = coords[(size_t)idx * 3 + (j - 16)];
        ctrs[j - 16] = c;
        g_ctr[i * 3 + (j - 16)] = c;
        g_feat[i * 35 + 32 + (j - 16)] = c;
    }
    if (j == 19) g_cb[i] = bidx[idx];
    __syncthreads();
    if (j < 337) {
        float a = bwg[j];
#pragma unroll
        for (int c = 0; c < 16; c++) a = fmaf(cks[c], Wwg[c * 337 + j], a);
        g_weights[i * 337 + j] = a;
        wrow[j] = a;
    }
    __syncthreads();
    if (j < 16) {
        float b = wrow[304 + j];
#pragma unroll
        for (int p = 0; p < 3; p++) b -= ctrs[p] * wrow[256 + p * 16 + j];
        g_beff[i * 16 + j] = b;
    }
}

// ---------------- dynamic-conv masks: 256-point tiles, streaming stores ----------------
__global__ __launch_bounds__(256) void masks_kernel(
    const float* __restrict__ coords, float* __restrict__ out, int N, int outw)
{
    extern __shared__ float dyn[];
    float* zs = dyn;                    // [19][MTILE+2]
    float* ot = dyn + 19 * (MTILE + 2); // [32][MTILE+1]

    int i_base = blockIdx.y * 32;
    int n0 = blockIdx.x * MTILE;
    int tid = threadIdx.x;
    int i_local = tid >> 3;
    int hg = tid & 7;
    int i = i_base + i_local;
    int h0 = hg * 2;

    const float* wi = g_weights + i * 337;
    ull w0[19], w1[19];
#pragma unroll
    for (int r = 0; r < 19; r++) {
        float a = wi[r * 16 + h0], b = wi[r * 16 + h0 + 1];
        w0[r] = pk2(a, a);
        w1[r] = pk2(b, b);
    }
    float be0f = g_beff[i * 16 + h0], be1f = g_beff[i * 16 + h0 + 1];
    ull be0 = pk2(be0f, be0f), be1 = pk2(be1f, be1f);
    float w2a = wi[320 + h0], w2b = wi[320 + h0 + 1];
    float b2 = wi[336];

    for (int idx = tid; idx < 16 * MTILE; idx += 256) {
        int c = idx >> 8, p = idx & (MTILE - 1);
        int n = n0 + p;
        zs[c * (MTILE + 2) + p] = (n < N) ? g_mask_feats[(size_t)c * N + n] : 0.f;
    }
    for (int idx = tid; idx < MTILE * 3; idx += 256) {
        int p = idx / 3, c = idx % 3;
        int n = n0 + p;
        zs[(16 + c) * (MTILE + 2) + p] = (n < N) ? coords[(size_t)n * 3 + c] : 0.f;
    }
    __syncthreads();

#pragma unroll 2
    for (int pp = 0; pp < MTILE / 2; pp++) {
        ull a0 = be0, a1 = be1;
#pragma unroll
        for (int r = 0; r < 19; r++) {
            ull z = *(const ull*)&zs[r * (MTILE + 2) + pp * 2];
            a0 = ffma2(z, w0[r], a0);
            a1 = ffma2(z, w1[r], a1);
        }
        float a0l, a0h, a1l, a1h;
        upk2(a0, a0l, a0h);
        upk2(a1, a1l, a1h);
        float pl = fmaf(fmaxf(a0l, 0.f), w2a, fmaxf(a1l, 0.f) * w2b);
        float ph = fmaf(fmaxf(a0h, 0.f), w2a, fmaxf(a1h, 0.f) * w2b);
        pl += __shfl_down_sync(0xffffffffu, pl, 4, 8);
        ph += __shfl_down_sync(0xffffffffu, ph, 4, 8);
        pl += __shfl_down_sync(0xffffffffu, pl, 2, 8);
        ph += __shfl_down_sync(0xffffffffu, ph, 2, 8);
        pl += __shfl_down_sync(0xffffffffu, pl, 1, 8);
        ph += __shfl_down_sync(0xffffffffu, ph, 1, 8);
        if (hg == 0) {
            ot[i_local * (MTILE + 1) + pp * 2]     = fast_sigmoid(pl + b2);
            ot[i_local * (MTILE + 1) + pp * 2 + 1] = fast_sigmoid(ph + b2);
        }
    }
    __syncthreads();

    for (int idx = tid; idx < 32 * MTILE; idx += 256) {
        int il = idx >> 8, p = idx & (MTILE - 1);
        int n = n0 + p;
        if (n < N) __stcs(&out[(size_t)(i_base + il) * outw + n], ot[il * (MTILE + 1) + p]);
    }
}

// ---------------- merge branch: fused diff + layer1 (stats -> stage 0) ----------------
__global__ __launch_bounds__(256) void diffM1_kernel(
    const float* __restrict__ Wg, float* __restrict__ outp)
{
    __shared__ float fs[128 * 35];
    __shared__ float Ws[1225];
    __shared__ double bsd[35], bqd[35];
    int tid = threadIdx.x;
    int lane = tid & 31;
    for (int t = tid; t < 128 * 35; t += 256) fs[t] = g_feat[t];
    for (int t = tid; t < 1225; t += 256) Ws[t] = Wg[t];
    if (tid < 35) { bsd[tid] = 0.0; bqd[tid] = 0.0; }
    __syncthreads();

    int p = blockIdx.x * 256 + tid;
    int i = p >> 7, j = p & 127;

    float acc[35];
#pragma unroll
    for (int d = 0; d < 35; d++) acc[d] = 0.f;
#pragma unroll
    for (int c = 0; c < 35; c++) {
        float x = fmaxf(fabsf(fs[i * 35 + c] - fs[j * 35 + c]), 1e-6f);
        const float* w = &Ws[c * 35];
#pragma unroll
        for (int d = 0; d < 35; d++) acc[d] = fmaf(x, w[d], acc[d]);
    }
#pragma unroll
    for (int d = 0; d < 35; d++) outp[(size_t)p * 35 + d] = acc[d];

#pragma unroll
    for (int d = 0; d < 35; d++) {
        float v = acc[d], q = v * v;
#pragma unroll
        for (int o = 16; o > 0; o >>= 1) {
            v += __shfl_down_sync(0xffffffffu, v, o);
            q += __shfl_down_sync(0xffffffffu, q, o);
        }
        if (lane == 0) { atomicAdd(&bsd[d], (double)v); atomicAdd(&bqd[d], (double)q); }
    }
    __syncthreads();
    if (tid < 35) {
        atomicAdd(&g_sumM[tid], bsd[tid]);
        atomicAdd(&g_sumsqM[tid], bqd[tid]);
    }
}

// ---------------- merge BN layer: stats stage SIN -> compute, accumulate SOUT ----------------
template <int SIN, int SOUT, bool STATS>
__global__ __launch_bounds__(256) void layerM3_kernel(
    const float* __restrict__ W, const float* __restrict__ in, float* __restrict__ outp)
{
    __shared__ float Ws[1225];
    __shared__ float sm[35], sr[35];
    __shared__ double bsd[35], bqd[35];
    int tid = threadIdx.x;
    int lane = tid & 31;
    for (int t = tid; t < 1225; t += 256) Ws[t] = W[t];
    if (tid < 35) {
        double m = g_sumM[SIN * 64 + tid] / 16384.0;
        double v = g_sumsqM[SIN * 64 + tid] / 16384.0 - m * m;
        sm[tid] = (float)m;
        sr[tid] = (float)(1.0 / sqrt(v + 1e-5));
        if (STATS) { bsd[tid] = 0.0; bqd[tid] = 0.0; }
    }
    __syncthreads();

    int p = blockIdx.x * 256 + tid;
    float acc[35];
#pragma unroll
    for (int d = 0; d < 35; d++) acc[d] = 0.f;
#pragma unroll
    for (int c = 0; c < 35; c++) {
        float x = fmaxf((in[(size_t)p * 35 + c] - sm[c]) * sr[c], 0.f);
        const float* w = &Ws[c * 35];
#pragma unroll
        for (int d = 0; d < 35; d++) acc[d] = fmaf(x, w[d], acc[d]);
    }
#pragma unroll
    for (int d = 0; d < 35; d++) outp[(size_t)p * 35 + d] = acc[d];

    if (STATS) {
#pragma unroll
        for (int d = 0; d < 35; d++) {
            float v = acc[d], q = v * v;
#pragma unroll
            for (int o = 16; o > 0; o >>= 1) {
                v += __shfl_down_sync(0xffffffffu, v, o);
                q += __shfl_down_sync(0xffffffffu, q, o);
            }
            if (lane == 0) { atomicAdd(&bsd[d], (double)v); atomicAdd(&bqd[d], (double)q); }
        }
        __syncthreads();
        if (tid < 35) {
            atomicAdd(&g_sumM[SOUT * 64 + tid], bsd[tid]);
            atomicAdd(&g_sumsqM[SOUT * 64 + tid], bqd[tid]);
        }
    }
}

// ---------------- merge output (stats stage 2 in-block) ----------------
__global__ __launch_bounds__(256) void merge_out3_kernel(
    const float* __restrict__ WgOut, const float* __restrict__ bg,
    const float* __restrict__ in, float* __restrict__ out, int N, int outw)
{
    __shared__ float sm[35], sr[35], wo[35];
    __shared__ float bgs;
    int tid = threadIdx.x;
    if (tid < 35) {
        double m = g_sumM[2 * 64 + tid] / 16384.0;
        double v = g_sumsqM[2 * 64 + tid] / 16384.0 - m * m;
        sm[tid] = (float)m;
        sr[tid] = (float)(1.0 / sqrt(v + 1e-5));
        wo[tid] = WgOut[tid];
    }
    if (tid == 35) bgs = bg[0];
    __syncthreads();

    int p = blockIdx.x * 256 + tid;
    int i = p >> 7, j = p & 127;
    float a = bgs;
#pragma unroll
    for (int c = 0; c < 35; c++) {
        float xv = fmaxf((in[(size_t)p * 35 + c] - sm[c]) * sr[c], 0.f);
        a = fmaf(xv, wo[c], a);
    }
    float m = (g_cb[i] != g_cb[j]) ? 0.f : fast_sigmoid(a);
    out[(size_t)i * outw + N + j] = m;
}

// ---------------- launcher ----------------
extern "C" void kernel_launch(void* const* d_in, const int* in_sizes, int n_in,
                              void* d_out, int out_size)
{
    const float* output_feats = (const float*)d_in[0];
    const float* coords       = (const float*)d_in[1];
    const float* heat         = (const float*)d_in[2];
    const int*   batch_idxs   = (const int*)d_in[3];
    const float* Wm     = (const float*)d_in[4];
    const float* Wm_out = (const float*)d_in[5];
    const float* bm_out = (const float*)d_in[6];
    const float* Wk     = (const float*)d_in[7];
    const float* Wk_out = (const float*)d_in[8];
    const float* bk_out = (const float*)d_in[9];
    const float* Wg     = (const float*)d_in[10];
    const float* Wg_out = (const float*)d_in[11];
    const float* bg_out = (const float*)d_in[12];
    const float* Wwg    = (const float*)d_in[13];
    const float* bwg    = (const float*)d_in[14];
    float* out = (float*)d_out;

    int N = in_sizes[2];
    int outw = N + I_CNT;
    int nb = (N + 255) / 256;
    int nb2 = (N + 511) / 512;

    float *tA, *tB, *maskf, *kernf, *pairA, *pairB;
    cudaGetSymbolAddress((void**)&tA,    g_tA);
    cudaGetSymbolAddress((void**)&tB,    g_tB);
    cudaGetSymbolAddress((void**)&maskf, g_mask_feats);
    cudaGetSymbolAddress((void**)&kernf, g_kern_feats);
    cudaGetSymbolAddress((void**)&pairA, g_pairA);
    cudaGetSymbolAddress((void**)&pairB, g_pairB);

    const int MASK_SMEM = (19 * (MTILE + 2) + 32 * (MTILE + 1)) * (int)sizeof(float);
    const int NMS_SMEM = 2 * NMS_SMEM_N * (int)sizeof(float);

    static cudaStream_t s1;
    static cudaEvent_t evFork1, evJoin1, evFork2, evJoin2;
    static bool init_done = false;
    if (!init_done) {
        cudaFuncSetAttribute(nms_kernel, cudaFuncAttributeMaxDynamicSharedMemorySize, NMS_SMEM);
        cudaFuncSetAttribute(masks_kernel, cudaFuncAttributeMaxDynamicSharedMemorySize, MASK_SMEM);
        cudaFuncSetAttribute(layerBN3_kernel<true>, cudaFuncAttributeMaxDynamicSharedMemorySize, BN3_SMEM);
        cudaFuncSetAttribute(layerOut3_kernel, cudaFuncAttributeMaxDynamicSharedMemorySize, OUT3_SMEM);
        cudaStreamCreateWithFlags(&s1, cudaStreamNonBlocking);
        cudaEventCreateWithFlags(&evFork1, cudaEventDisableTiming);
        cudaEventCreateWithFlags(&evJoin1, cudaEventDisableTiming);
        cudaEventCreateWithFlags(&evFork2, cudaEventDisableTiming);
        cudaEventCreateWithFlags(&evJoin2, cudaEventDisableTiming);
        init_done = true;
    }

    prologue_kernel<<<nb, 256>>>(batch_idxs, N);

    cudaEventRecord(evFork1, 0);
    cudaStreamWaitEvent(s1, evFork1, 0);
    nms_kernel<<<4, 1024, NMS_SMEM, s1>>>(heat, coords, N);
    cudaEventRecord(evJoin1, s1);

    // tower chain (fused stats, 2-point f32x2 BN/Out layers)
    dim3 g2(nb2, 2);
    layer0_kernel<<<nb, 256>>>(output_feats, Wm, Wk, tA, N);
    layerBN3_kernel<true><<<g2, 256, BN3_SMEM>>>(tA, Wm + 1024, Wk + 1024, tB, N, 0, 1);
    layerBN3_kernel<true><<<g2, 256, BN3_SMEM>>>(tB, Wm + 2048, Wk + 2048, tA, N, 1, 2);
    layerOut3_kernel<<<g2, 256, OUT3_SMEM>>>(tA, Wm_out, Wk_out, bm_out, bk_out, maskf, kernf, N, 2);

    cudaStreamWaitEvent(0, evJoin1, 0);
    gwb_kernel<<<I_CNT, 352>>>(coords, batch_idxs, Wwg, bwg, N);

    cudaEventRecord(evFork2, 0);
    cudaStreamWaitEvent(s1, evFork2, 0);
    diffM1_kernel<<<64, 256, 0, s1>>>(Wg, pairA);
    layerM3_kernel<0, 1, true><<<64, 256, 0, s1>>>(Wg + 1225, pairA, pairB);
    layerM3_kernel<1, 2, true><<<64, 256, 0, s1>>>(Wg + 2450, pairB, pairA);
    merge_out3_kernel<<<64, 256, 0, s1>>>(Wg_out, bg_out, pairA, out, N, outw);
    cudaEventRecord(evJoin2, s1);

    dim3 mg((N + MTILE - 1) / MTILE, 4);
    masks_kernel<<<mg, 256, MASK_SMEM>>>(coords, out, N, outw);

    cudaStreamWaitEvent(0, evJoin2, 0);
}